// round 13
// baseline (speedup 1.0000x reference)
#include <cuda_runtime.h>
#include <cuda_fp16.h>

#define FDIM 128
#define F2   16
#define NMAX 100000
#define EMAX 1600000
#define SCAN_TPB 1024
#define NBLK ((NMAX + SCAN_TPB - 1) / SCAN_TPB)   // 98
#define WP_STRIDE 136                              // packed-W smem row stride (words)

// ---- device scratch (static allocation; no cudaMalloc allowed) ----
__device__ float  g_dinv[NMAX];                  // deg^{-1/2}
__device__ int    g_deg[NMAX];                   // in-degree histogram (per-launch zeroed)
__device__ int    g_rowstart[NMAX + 1];          // CSR row offsets (by dst)
__device__ int    g_cur[NMAX];                   // CSR fill cursors
__device__ int    g_csr[EMAX];                   // CSR column (src) indices
__device__ int    g_bsum[NBLK];                  // per-block degree sums
__device__ __half g_h0[(size_t)NMAX * FDIM];     // raw x@W1, fp16
__device__ float  g_h1[(size_t)NMAX * FDIM];     // relu(aggregated layer 1)
__device__ __half g_t2[(size_t)NMAX * F2];       // (h1@W2)*dinv[row], fp16
__device__ int    g_idx64;                       // 1 if edge_index is int64, 0 if int32

// Flag-dispatched edge read (handles int64 vs int32 edge_index).
__device__ __forceinline__ int edge_at(const void* ei, long long i) {
    if (g_idx64) return (int)((const long long*)ei)[i];
    return ((const int*)ei)[i];
}

// Pack two floats into an fp16x2 word (low = first).
__device__ __forceinline__ unsigned pack_h2(float a, float b) {
    __half2 h = __floats2half2_rn(a, b);
    return *(unsigned*)&h;
}

__device__ __forceinline__ void mma_f16(float* d, unsigned a0, unsigned a1,
                                        unsigned a2, unsigned a3,
                                        unsigned b0, unsigned b1) {
    asm volatile(
        "mma.sync.aligned.m16n8k16.row.col.f32.f16.f16.f32 "
        "{%0,%1,%2,%3}, {%4,%5,%6,%7}, {%8,%9}, {%0,%1,%2,%3};"
        : "+f"(d[0]), "+f"(d[1]), "+f"(d[2]), "+f"(d[3])
        : "r"(a0), "r"(a1), "r"(a2), "r"(a3), "r"(b0), "r"(b1));
}

// ---- K1: zero degree histogram; warp 0 of block 0 probes edge dtype. ----
__global__ void zero_probe_k(const unsigned long long* __restrict__ ei, int n) {
    int i = blockIdx.x * blockDim.x + threadIdx.x;
    if (i < n) g_deg[i] = 0;
    if (blockIdx.x == 0 && threadIdx.x < 32) {
        unsigned long long hi = 0;
        #pragma unroll
        for (int j = 0; j < 8; j++) hi |= ei[threadIdx.x + j * 32] >> 32;
        int any = __any_sync(0xffffffffu, hi != 0);
        if (threadIdx.x == 0) g_idx64 = any ? 0 : 1;
    }
}

// ---- K2 (fused): blocks [0, gemm_blocks) compute raw g_h0 = x @ W1 via
// 2-term fp16-split MMA; remaining blocks do the in-degree histogram.
// Independent jobs; gemm1 smem is only 34.8KB so hist blocks still get
// 6 blocks/SM (1536 thr) -- plenty for an L2-atomic-bound histogram. ----
__global__ void __launch_bounds__(256, 3) histgemm_k(
        const float* __restrict__ x, const float* __restrict__ W1,
        const void* __restrict__ ei, int n, int e, int gemm_blocks) {
    if (blockIdx.x >= gemm_blocks) {
        long long b = blockIdx.x - gemm_blocks;
        long long t = b * blockDim.x + threadIdx.x;
        if (t < e) {
            int d = edge_at(ei, (long long)e + t);
            atomicAdd(&g_deg[d], 1);
        }
        return;
    }

    // --- GEMM part: A = Ah + Al (exact to 2^-21), B fp16-truncated in smem.
    // D = Ah*Bh + Al*Bh. Warp tile 16x128; block tile 128 rows. ---
    extern __shared__ unsigned Wsm[];    // [64][WP_STRIDE]: word [kp][n] = fp16x2
    int tid = threadIdx.x;
    int warp = tid >> 5, lane = tid & 31;

    #pragma unroll
    for (int i = 0; i < 32; i++) {
        int p = i * 256 + tid;
        int kp = p >> 7, nn = p & 127;
        Wsm[kp * WP_STRIDE + nn] = pack_h2(W1[(2 * kp) * FDIM + nn],
                                           W1[(2 * kp + 1) * FDIM + nn]);
    }
    __syncthreads();

    int r_base = blockIdx.x * 128 + warp * 16;
    int row_a = r_base + (lane >> 2);    // fragment row (lower 8)
    int tig   = lane & 3;                // thread-in-group
    int colw  = lane >> 2;               // fragment column within 8

    float acc[16][4];
    #pragma unroll
    for (int nt = 0; nt < 16; nt++) {
        acc[nt][0] = acc[nt][1] = acc[nt][2] = acc[nt][3] = 0.0f;
    }

    bool v0 = row_a < n, v1 = row_a + 8 < n;
    const float zero2[2] = {0.0f, 0.0f};

    #pragma unroll
    for (int ks = 0; ks < 8; ks++) {
        int k0 = ks * 16;
        float2 xa = v0 ? *(const float2*)&x[(size_t)row_a * FDIM + k0 + tig * 2]           : *(const float2*)zero2;
        float2 xb = v0 ? *(const float2*)&x[(size_t)row_a * FDIM + k0 + 8 + tig * 2]       : *(const float2*)zero2;
        float2 xc = v1 ? *(const float2*)&x[(size_t)(row_a + 8) * FDIM + k0 + tig * 2]     : *(const float2*)zero2;
        float2 xd = v1 ? *(const float2*)&x[(size_t)(row_a + 8) * FDIM + k0 + 8 + tig * 2] : *(const float2*)zero2;

        unsigned ah0 = pack_h2(xa.x, xa.y), ah1 = pack_h2(xc.x, xc.y);
        unsigned ah2 = pack_h2(xb.x, xb.y), ah3 = pack_h2(xd.x, xd.y);
        __half2 h0 = *(__half2*)&ah0, h1 = *(__half2*)&ah1;
        __half2 h2 = *(__half2*)&ah2, h3 = *(__half2*)&ah3;
        unsigned al0 = pack_h2(xa.x - __half2float(h0.x), xa.y - __half2float(h0.y));
        unsigned al1 = pack_h2(xc.x - __half2float(h1.x), xc.y - __half2float(h1.y));
        unsigned al2 = pack_h2(xb.x - __half2float(h2.x), xb.y - __half2float(h2.y));
        unsigned al3 = pack_h2(xd.x - __half2float(h3.x), xd.y - __half2float(h3.y));

        int o0 = (ks * 8 + tig) * WP_STRIDE + colw;        // k-pairs k0..k0+7
        int o1 = (ks * 8 + 4 + tig) * WP_STRIDE + colw;    // k-pairs k0+8..k0+15
        #pragma unroll
        for (int nt = 0; nt < 16; nt++) {
            unsigned bh0 = Wsm[o0 + nt * 8];
            unsigned bh1 = Wsm[o1 + nt * 8];
            mma_f16(acc[nt], ah0, ah1, ah2, ah3, bh0, bh1);
            mma_f16(acc[nt], al0, al1, al2, al3, bh0, bh1);
        }
    }

    // Epilogue: store RAW h0 (dinv applied in pull1's gather).
    #pragma unroll
    for (int nt = 0; nt < 16; nt++) {
        int col = nt * 8 + tig * 2;
        if (v0) {
            __half2 v = __floats2half2_rn(acc[nt][0], acc[nt][1]);
            *(__half2*)&g_h0[(size_t)row_a * FDIM + col] = v;
        }
        if (v1) {
            __half2 v = __floats2half2_rn(acc[nt][2], acc[nt][3]);
            *(__half2*)&g_h0[(size_t)(row_a + 8) * FDIM + col] = v;
        }
    }
}

// Block-wide inclusive scan of one value per thread (1024 threads, 32 warps).
__device__ __forceinline__ int block_scan_1024(int v, int* block_total, int* wsum) {
    int lane = threadIdx.x & 31, w = threadIdx.x >> 5;
    int x = v;
    #pragma unroll
    for (int o = 1; o < 32; o <<= 1) {
        int y = __shfl_up_sync(0xffffffffu, x, o);
        if (lane >= o) x += y;
    }
    if (lane == 31) wsum[w] = x;
    __syncthreads();
    if (w == 0) {
        int s = wsum[lane];
        #pragma unroll
        for (int o = 1; o < 32; o <<= 1) {
            int y = __shfl_up_sync(0xffffffffu, s, o);
            if (lane >= o) s += y;
        }
        wsum[lane] = s;
    }
    __syncthreads();
    int incl = x + (w > 0 ? wsum[w - 1] : 0);
    *block_total = wsum[31];
    return incl;
}

// ---- K3a: per-block degree sums; also computes dinv ----
__global__ void scan_phase1_k(int n) {
    __shared__ int wsum[32];
    int i = blockIdx.x * SCAN_TPB + threadIdx.x;
    int v = (i < n) ? g_deg[i] : 0;
    int total;
    block_scan_1024(v, &total, wsum);
    if (threadIdx.x == 0) g_bsum[blockIdx.x] = total;
    if (i < n) g_dinv[i] = rsqrtf((float)(v + 1));   // self-loop adds 1
}

// ---- K3b: local scan; each block computes its own prefix over g_bsum ----
__global__ void scan_phase3_k(int n) {
    __shared__ int wsum[32];
    __shared__ int s_boff;
    if (threadIdx.x < 32) {
        int sum = 0;
        for (int j = threadIdx.x; j < blockIdx.x; j += 32) sum += g_bsum[j];
        #pragma unroll
        for (int o = 16; o > 0; o >>= 1) sum += __shfl_down_sync(0xffffffffu, sum, o);
        if (threadIdx.x == 0) s_boff = sum;
    }
    int i = blockIdx.x * SCAN_TPB + threadIdx.x;
    int v = (i < n) ? g_deg[i] : 0;
    int total;
    int incl = block_scan_1024(v, &total, wsum);
    int boff = s_boff;
    if (i < n) {
        int excl = boff + incl - v;
        g_rowstart[i] = excl;
        g_cur[i] = excl;
    }
    if (blockIdx.x == gridDim.x - 1 && threadIdx.x == 0)
        g_rowstart[n] = boff + total;
}

// ---- K4: fill CSR (src ids bucketed by dst) ----
__global__ void fill_k(const void* __restrict__ ei, int e) {
    long long t = (long long)blockIdx.x * blockDim.x + threadIdx.x;
    if (t < e) {
        int s = edge_at(ei, t);
        int d = edge_at(ei, (long long)e + t);
        int pos = atomicAdd(&g_cur[d], 1);
        g_csr[pos] = s;
    }
}

// ---- K6: pull-mode layer-1 aggregation + fused finalize.
//          One warp per dst node; lane owns 4 features (8B fp16 load).
//          h0 is raw, so dinv[src] applied per neighbor (broadcast L1 load). ----
__global__ void pull1_k(const float* __restrict__ b1, int n) {
    int wid_g = (blockIdx.x * blockDim.x + threadIdx.x) >> 5;
    int lane = threadIdx.x & 31;
    if (wid_g >= n) return;
    int beg = g_rowstart[wid_g];
    int end = g_rowstart[wid_g + 1];
    const uint2* H0 = (const uint2*)g_h0;
    float di = g_dinv[wid_g];

    uint2 sv = H0[(size_t)wid_g * 32 + lane];            // self-loop term (raw)
    float2 s0 = __half22float2(*(const __half2*)&sv.x);
    float2 s1 = __half22float2(*(const __half2*)&sv.y);
    float4 acc = make_float4(s0.x * di, s0.y * di, s1.x * di, s1.y * di);

    for (int j0 = beg; j0 < end; j0 += 32) {
        int id = (j0 + lane < end) ? g_csr[j0 + lane] : 0;   // one coalesced load
        int m = min(32, end - j0);
        for (int jj = 0; jj < m; jj += 8) {
            #pragma unroll
            for (int k = 0; k < 8; k++) {
                int j = jj + k;
                int s = __shfl_sync(0xffffffffu, id, j & 31);
                if (j < m) {
                    float ds = g_dinv[s];                    // broadcast load
                    uint2 v = H0[(size_t)s * 32 + lane];
                    float2 p0 = __half22float2(*(const __half2*)&v.x);
                    float2 p1 = __half22float2(*(const __half2*)&v.y);
                    acc.x = fmaf(p0.x, ds, acc.x);
                    acc.y = fmaf(p0.y, ds, acc.y);
                    acc.z = fmaf(p1.x, ds, acc.z);
                    acc.w = fmaf(p1.y, ds, acc.w);
                }
            }
        }
    }
    float4 bb = ((const float4*)b1)[lane];
    acc.x = fmaxf(fmaf(acc.x, di, bb.x), 0.0f);
    acc.y = fmaxf(fmaf(acc.y, di, bb.y), 0.0f);
    acc.z = fmaxf(fmaf(acc.z, di, bb.z), 0.0f);
    acc.w = fmaxf(fmaf(acc.w, di, bb.w), 0.0f);
    ((float4*)g_h1)[(size_t)wid_g * 32 + lane] = acc;
}

// ---- K7: g_t2 = (h1 @ W2) * dinv[row], fp16 out ----
__global__ void gemm2_k(const float* __restrict__ W2, int n) {
    __shared__ float ws[FDIM * F2];
    __shared__ float hs[8][FDIM];
    int tid = threadIdx.x;               // 128 threads
    #pragma unroll
    for (int i = 0; i < F2; i++) ws[i * FDIM + tid] = W2[i * FDIM + tid];
    long long r0 = (long long)blockIdx.x * 8;
    #pragma unroll
    for (int j = 0; j < 8; j++) {
        long long r = r0 + j;
        hs[j][tid] = (r < n) ? g_h1[r * FDIM + tid] : 0.0f;
    }
    __syncthreads();
    int lr = tid >> 4;                   // local row 0..7
    int c  = tid & 15;                   // col 0..15
    float acc = 0.0f;
    #pragma unroll 8
    for (int k = 0; k < FDIM; k++) acc = fmaf(hs[lr][k], ws[k * F2 + c], acc);
    long long r = r0 + lr;
    if (r < n) g_t2[r * F2 + c] = __float2half_rn(acc * g_dinv[r]);
}

// ---- K8: pull-mode layer-2 aggregation + fused finalize, writes d_out. ----
__global__ void pull2_k(const float* __restrict__ b2, float* __restrict__ out, int n) {
    int t = blockIdx.x * blockDim.x + threadIdx.x;
    if (t >= n * 4) return;
    int node = t >> 2, q = t & 3;
    int beg = g_rowstart[node];
    int end = g_rowstart[node + 1];
    const uint2* T2 = (const uint2*)g_t2;

    uint2 sv = T2[(size_t)node * 4 + q];                 // self-loop term
    float2 s0 = __half22float2(*(const __half2*)&sv.x);
    float2 s1 = __half22float2(*(const __half2*)&sv.y);
    float4 acc = make_float4(s0.x, s0.y, s1.x, s1.y);

    #pragma unroll 4
    for (int j = beg; j < end; j++) {
        int s = __ldg(&g_csr[j]);
        uint2 v = T2[(size_t)s * 4 + q];
        float2 p0 = __half22float2(*(const __half2*)&v.x);
        float2 p1 = __half22float2(*(const __half2*)&v.y);
        acc.x += p0.x; acc.y += p0.y; acc.z += p1.x; acc.w += p1.y;
    }
    float di = g_dinv[node];
    float4 bb = ((const float4*)b2)[q];
    acc.x = fmaf(acc.x, di, bb.x);
    acc.y = fmaf(acc.y, di, bb.y);
    acc.z = fmaf(acc.z, di, bb.z);
    acc.w = fmaf(acc.w, di, bb.w);
    ((float4*)out)[(size_t)node * 4 + q] = acc;
}

extern "C" void kernel_launch(void* const* d_in, const int* in_sizes, int n_in,
                              void* d_out, int out_size) {
    const float* x  = (const float*)d_in[0];
    const void*  ei = d_in[1];
    const float* W1 = (const float*)d_in[2];
    const float* b1 = (const float*)d_in[3];
    const float* W2 = (const float*)d_in[4];
    const float* b2 = (const float*)d_in[5];
    float* out = (float*)d_out;

    int n = in_sizes[0] / FDIM;   // 100000
    int e = in_sizes[1] / 2;      // 1600000

    const int ws_bytes = 64 * WP_STRIDE * sizeof(unsigned);  // 34816
    cudaFuncSetAttribute(histgemm_k, cudaFuncAttributeMaxDynamicSharedMemorySize, ws_bytes);

    int nblk = (n + SCAN_TPB - 1) / SCAN_TPB;
    int gemm_blocks = (n + 127) / 128;           // 782
    int hist_blocks = (e + 255) / 256;           // 6250

    zero_probe_k<<<(n + 255) / 256, 256>>>((const unsigned long long*)ei, n);     // 1
    histgemm_k<<<gemm_blocks + hist_blocks, 256, ws_bytes>>>(x, W1, ei, n, e,
                                                             gemm_blocks);        // 2
    scan_phase1_k<<<nblk, SCAN_TPB>>>(n);                                         // 3
    scan_phase3_k<<<nblk, SCAN_TPB>>>(n);                                         // 4
    fill_k<<<(e + 255) / 256, 256>>>(ei, e);                                      // 5

    long long w1t = (long long)n * 32;   // one warp per node
    pull1_k<<<(unsigned)((w1t + 255) / 256), 256>>>(b1, n);                       // 6

    gemm2_k<<<(n + 7) / 8, 128>>>(W2, n);                                         // 7

    long long p2t = (long long)n * 4;    // 4 threads per node
    pull2_k<<<(unsigned)((p2t + 255) / 256), 256>>>(b2, out, n);                  // 8
}

// round 14
// speedup vs baseline: 1.0428x; 1.0428x over previous
#include <cuda_runtime.h>
#include <cuda_fp16.h>

#define FDIM 128
#define F2   16
#define NMAX 100000
#define EMAX 1600000
#define SCAN_TPB 1024
#define NBLK ((NMAX + SCAN_TPB - 1) / SCAN_TPB)   // 98
#define WP_STRIDE 136                              // packed-W smem row stride (words)

// ---- device scratch (static allocation; no cudaMalloc allowed) ----
__device__ float  g_dinv[NMAX];                  // deg^{-1/2}
__device__ int    g_deg[NMAX];                   // in-degree histogram (per-launch zeroed)
__device__ int    g_rowstart[NMAX + 1];          // CSR row offsets (by dst)
__device__ int    g_cur[NMAX];                   // CSR fill cursors
__device__ int    g_csr[EMAX];                   // CSR column (src) indices
__device__ int    g_bsum[NBLK];                  // per-block degree sums
__device__ __half g_h0[(size_t)NMAX * FDIM];     // (x@W1)*dinv[row], fp16
__device__ __half g_h1[(size_t)NMAX * FDIM];     // relu(aggregated layer 1), fp16
__device__ __half g_t2[(size_t)NMAX * F2];       // (h1@W2)*dinv[row], fp16
__device__ int    g_idx64;                       // 1 if edge_index is int64, 0 if int32

// Flag-dispatched edge read (handles int64 vs int32 edge_index).
__device__ __forceinline__ int edge_at(const void* ei, long long i) {
    if (g_idx64) return (int)((const long long*)ei)[i];
    return ((const int*)ei)[i];
}

// Pack two floats into an fp16x2 word (low = first).
__device__ __forceinline__ unsigned pack_h2(float a, float b) {
    __half2 h = __floats2half2_rn(a, b);
    return *(unsigned*)&h;
}

__device__ __forceinline__ void mma_f16(float* d, unsigned a0, unsigned a1,
                                        unsigned a2, unsigned a3,
                                        unsigned b0, unsigned b1) {
    asm volatile(
        "mma.sync.aligned.m16n8k16.row.col.f32.f16.f16.f32 "
        "{%0,%1,%2,%3}, {%4,%5,%6,%7}, {%8,%9}, {%0,%1,%2,%3};"
        : "+f"(d[0]), "+f"(d[1]), "+f"(d[2]), "+f"(d[3])
        : "r"(a0), "r"(a1), "r"(a2), "r"(a3), "r"(b0), "r"(b1));
}

// ---- K1: zero degree histogram; warp 0 of block 0 probes edge dtype. ----
__global__ void zero_probe_k(const unsigned long long* __restrict__ ei, int n) {
    int i = blockIdx.x * blockDim.x + threadIdx.x;
    if (i < n) g_deg[i] = 0;
    if (blockIdx.x == 0 && threadIdx.x < 32) {
        unsigned long long hi = 0;
        #pragma unroll
        for (int j = 0; j < 8; j++) hi |= ei[threadIdx.x + j * 32] >> 32;
        int any = __any_sync(0xffffffffu, hi != 0);
        if (threadIdx.x == 0) g_idx64 = any ? 0 : 1;
    }
}

// ---- K2: in-degree histogram over dst (standalone; no smem reservation) ----
__global__ void hist_k(const void* __restrict__ ei, int e) {
    long long t = (long long)blockIdx.x * blockDim.x + threadIdx.x;
    if (t < e) {
        int d = edge_at(ei, (long long)e + t);
        atomicAdd(&g_deg[d], 1);
    }
}

// Block-wide inclusive scan of one value per thread (1024 threads, 32 warps).
__device__ __forceinline__ int block_scan_1024(int v, int* block_total, int* wsum) {
    int lane = threadIdx.x & 31, w = threadIdx.x >> 5;
    int x = v;
    #pragma unroll
    for (int o = 1; o < 32; o <<= 1) {
        int y = __shfl_up_sync(0xffffffffu, x, o);
        if (lane >= o) x += y;
    }
    if (lane == 31) wsum[w] = x;
    __syncthreads();
    if (w == 0) {
        int s = wsum[lane];
        #pragma unroll
        for (int o = 1; o < 32; o <<= 1) {
            int y = __shfl_up_sync(0xffffffffu, s, o);
            if (lane >= o) s += y;
        }
        wsum[lane] = s;
    }
    __syncthreads();
    int incl = x + (w > 0 ? wsum[w - 1] : 0);
    *block_total = wsum[31];
    return incl;
}

// ---- K3a: per-block degree sums; also computes dinv ----
__global__ void scan_phase1_k(int n) {
    __shared__ int wsum[32];
    int i = blockIdx.x * SCAN_TPB + threadIdx.x;
    int v = (i < n) ? g_deg[i] : 0;
    int total;
    block_scan_1024(v, &total, wsum);
    if (threadIdx.x == 0) g_bsum[blockIdx.x] = total;
    if (i < n) g_dinv[i] = rsqrtf((float)(v + 1));   // self-loop adds 1
}

// ---- K3b: local scan; each block computes its own prefix over g_bsum ----
__global__ void scan_phase3_k(int n) {
    __shared__ int wsum[32];
    __shared__ int s_boff;
    if (threadIdx.x < 32) {
        int sum = 0;
        for (int j = threadIdx.x; j < blockIdx.x; j += 32) sum += g_bsum[j];
        #pragma unroll
        for (int o = 16; o > 0; o >>= 1) sum += __shfl_down_sync(0xffffffffu, sum, o);
        if (threadIdx.x == 0) s_boff = sum;
    }
    int i = blockIdx.x * SCAN_TPB + threadIdx.x;
    int v = (i < n) ? g_deg[i] : 0;
    int total;
    int incl = block_scan_1024(v, &total, wsum);
    int boff = s_boff;
    if (i < n) {
        int excl = boff + incl - v;
        g_rowstart[i] = excl;
        g_cur[i] = excl;
    }
    if (blockIdx.x == gridDim.x - 1 && threadIdx.x == 0)
        g_rowstart[n] = boff + total;
}

// ---- K4: fill CSR (src ids bucketed by dst) ----
__global__ void fill_k(const void* __restrict__ ei, int e) {
    long long t = (long long)blockIdx.x * blockDim.x + threadIdx.x;
    if (t < e) {
        int s = edge_at(ei, t);
        int d = edge_at(ei, (long long)e + t);
        int pos = atomicAdd(&g_cur[d], 1);
        g_csr[pos] = s;
    }
}

// ---- K5: g_h0 = (x @ W1) * dinv[row] (fp16 out) via 2-term fp16-split MMA.
// A = Ah + Al (exact to 2^-21); B truncated to fp16 in smem.
// D = Ah*Bh + Al*Bh = A*Bh. 8 warps/block; warp tile 16x128. ----
__global__ void __launch_bounds__(256, 3) gemm1_k(
        const float* __restrict__ x, const float* __restrict__ W1, int n) {
    extern __shared__ unsigned Wsm[];    // [64][WP_STRIDE]: word [kp][n] = fp16x2
    int tid = threadIdx.x;
    int warp = tid >> 5, lane = tid & 31;

    #pragma unroll
    for (int i = 0; i < 32; i++) {
        int p = i * 256 + tid;
        int kp = p >> 7, nn = p & 127;
        Wsm[kp * WP_STRIDE + nn] = pack_h2(W1[(2 * kp) * FDIM + nn],
                                           W1[(2 * kp + 1) * FDIM + nn]);
    }
    __syncthreads();

    int r_base = blockIdx.x * 128 + warp * 16;
    int row_a = r_base + (lane >> 2);    // fragment row (lower 8)
    int tig   = lane & 3;                // thread-in-group
    int colw  = lane >> 2;               // fragment column within 8

    float acc[16][4];
    #pragma unroll
    for (int nt = 0; nt < 16; nt++) {
        acc[nt][0] = acc[nt][1] = acc[nt][2] = acc[nt][3] = 0.0f;
    }

    bool v0 = row_a < n, v1 = row_a + 8 < n;
    const float zero2[2] = {0.0f, 0.0f};

    #pragma unroll
    for (int ks = 0; ks < 8; ks++) {
        int k0 = ks * 16;
        float2 xa = v0 ? *(const float2*)&x[(size_t)row_a * FDIM + k0 + tig * 2]           : *(const float2*)zero2;
        float2 xb = v0 ? *(const float2*)&x[(size_t)row_a * FDIM + k0 + 8 + tig * 2]       : *(const float2*)zero2;
        float2 xc = v1 ? *(const float2*)&x[(size_t)(row_a + 8) * FDIM + k0 + tig * 2]     : *(const float2*)zero2;
        float2 xd = v1 ? *(const float2*)&x[(size_t)(row_a + 8) * FDIM + k0 + 8 + tig * 2] : *(const float2*)zero2;

        unsigned ah0 = pack_h2(xa.x, xa.y), ah1 = pack_h2(xc.x, xc.y);
        unsigned ah2 = pack_h2(xb.x, xb.y), ah3 = pack_h2(xd.x, xd.y);
        __half2 h0 = *(__half2*)&ah0, h1 = *(__half2*)&ah1;
        __half2 h2 = *(__half2*)&ah2, h3 = *(__half2*)&ah3;
        unsigned al0 = pack_h2(xa.x - __half2float(h0.x), xa.y - __half2float(h0.y));
        unsigned al1 = pack_h2(xc.x - __half2float(h1.x), xc.y - __half2float(h1.y));
        unsigned al2 = pack_h2(xb.x - __half2float(h2.x), xb.y - __half2float(h2.y));
        unsigned al3 = pack_h2(xd.x - __half2float(h3.x), xd.y - __half2float(h3.y));

        int o0 = (ks * 8 + tig) * WP_STRIDE + colw;        // k-pairs k0..k0+7
        int o1 = (ks * 8 + 4 + tig) * WP_STRIDE + colw;    // k-pairs k0+8..k0+15
        #pragma unroll
        for (int nt = 0; nt < 16; nt++) {
            unsigned bh0 = Wsm[o0 + nt * 8];
            unsigned bh1 = Wsm[o1 + nt * 8];
            mma_f16(acc[nt], ah0, ah1, ah2, ah3, bh0, bh1);
            mma_f16(acc[nt], al0, al1, al2, al3, bh0, bh1);
        }
    }

    // Epilogue: scale by dinv[row], store fp16 pairs.
    float di0 = v0 ? g_dinv[row_a]     : 0.0f;
    float di1 = v1 ? g_dinv[row_a + 8] : 0.0f;
    #pragma unroll
    for (int nt = 0; nt < 16; nt++) {
        int col = nt * 8 + tig * 2;
        if (v0) {
            __half2 v = __floats2half2_rn(acc[nt][0] * di0, acc[nt][1] * di0);
            *(__half2*)&g_h0[(size_t)row_a * FDIM + col] = v;
        }
        if (v1) {
            __half2 v = __floats2half2_rn(acc[nt][2] * di1, acc[nt][3] * di1);
            *(__half2*)&g_h0[(size_t)(row_a + 8) * FDIM + col] = v;
        }
    }
}

// ---- K6: pull-mode layer-1 aggregation + fused finalize; fp16 h1 out. ----
__global__ void pull1_k(const float* __restrict__ b1, int n) {
    int wid_g = (blockIdx.x * blockDim.x + threadIdx.x) >> 5;
    int lane = threadIdx.x & 31;
    if (wid_g >= n) return;
    int beg = g_rowstart[wid_g];
    int end = g_rowstart[wid_g + 1];
    const uint2* H0 = (const uint2*)g_h0;

    uint2 sv = H0[(size_t)wid_g * 32 + lane];            // self-loop term
    float2 s0 = __half22float2(*(const __half2*)&sv.x);
    float2 s1 = __half22float2(*(const __half2*)&sv.y);
    float4 acc = make_float4(s0.x, s0.y, s1.x, s1.y);

    for (int j0 = beg; j0 < end; j0 += 32) {
        int id = (j0 + lane < end) ? g_csr[j0 + lane] : 0;   // one coalesced load
        int m = min(32, end - j0);
        for (int jj = 0; jj < m; jj += 8) {
            #pragma unroll
            for (int k = 0; k < 8; k++) {
                int j = jj + k;
                int s = __shfl_sync(0xffffffffu, id, j & 31);
                if (j < m) {
                    uint2 v = H0[(size_t)s * 32 + lane];
                    float2 p0 = __half22float2(*(const __half2*)&v.x);
                    float2 p1 = __half22float2(*(const __half2*)&v.y);
                    acc.x += p0.x; acc.y += p0.y; acc.z += p1.x; acc.w += p1.y;
                }
            }
        }
    }
    float di = g_dinv[wid_g];
    float4 bb = ((const float4*)b1)[lane];
    acc.x = fmaxf(fmaf(acc.x, di, bb.x), 0.0f);
    acc.y = fmaxf(fmaf(acc.y, di, bb.y), 0.0f);
    acc.z = fmaxf(fmaf(acc.z, di, bb.z), 0.0f);
    acc.w = fmaxf(fmaf(acc.w, di, bb.w), 0.0f);
    uint2 hv;
    hv.x = pack_h2(acc.x, acc.y);
    hv.y = pack_h2(acc.z, acc.w);
    ((uint2*)g_h1)[(size_t)wid_g * 32 + lane] = hv;
}

// ---- K7: g_t2 = (h1 @ W2) * dinv[row], fp16 in/out ----
__global__ void gemm2_k(const float* __restrict__ W2, int n) {
    __shared__ float ws[FDIM * F2];
    __shared__ float hs[8][FDIM];
    int tid = threadIdx.x;               // 128 threads
    #pragma unroll
    for (int i = 0; i < F2; i++) ws[i * FDIM + tid] = W2[i * FDIM + tid];
    long long r0 = (long long)blockIdx.x * 8;
    #pragma unroll
    for (int j = 0; j < 8; j++) {
        long long r = r0 + j;
        hs[j][tid] = (r < n) ? __half2float(g_h1[r * FDIM + tid]) : 0.0f;
    }
    __syncthreads();
    int lr = tid >> 4;                   // local row 0..7
    int c  = tid & 15;                   // col 0..15
    float acc = 0.0f;
    #pragma unroll 8
    for (int k = 0; k < FDIM; k++) acc = fmaf(hs[lr][k], ws[k * F2 + c], acc);
    long long r = r0 + lr;
    if (r < n) g_t2[r * F2 + c] = __float2half_rn(acc * g_dinv[r]);
}

// ---- K8: pull-mode layer-2 aggregation + fused finalize, writes d_out. ----
__global__ void pull2_k(const float* __restrict__ b2, float* __restrict__ out, int n) {
    int t = blockIdx.x * blockDim.x + threadIdx.x;
    if (t >= n * 4) return;
    int node = t >> 2, q = t & 3;
    int beg = g_rowstart[node];
    int end = g_rowstart[node + 1];
    const uint2* T2 = (const uint2*)g_t2;

    uint2 sv = T2[(size_t)node * 4 + q];                 // self-loop term
    float2 s0 = __half22float2(*(const __half2*)&sv.x);
    float2 s1 = __half22float2(*(const __half2*)&sv.y);
    float4 acc = make_float4(s0.x, s0.y, s1.x, s1.y);

    #pragma unroll 4
    for (int j = beg; j < end; j++) {
        int s = __ldg(&g_csr[j]);
        uint2 v = T2[(size_t)s * 4 + q];
        float2 p0 = __half22float2(*(const __half2*)&v.x);
        float2 p1 = __half22float2(*(const __half2*)&v.y);
        acc.x += p0.x; acc.y += p0.y; acc.z += p1.x; acc.w += p1.y;
    }
    float di = g_dinv[node];
    float4 bb = ((const float4*)b2)[q];
    acc.x = fmaf(acc.x, di, bb.x);
    acc.y = fmaf(acc.y, di, bb.y);
    acc.z = fmaf(acc.z, di, bb.z);
    acc.w = fmaf(acc.w, di, bb.w);
    ((float4*)out)[(size_t)node * 4 + q] = acc;
}

extern "C" void kernel_launch(void* const* d_in, const int* in_sizes, int n_in,
                              void* d_out, int out_size) {
    const float* x  = (const float*)d_in[0];
    const void*  ei = d_in[1];
    const float* W1 = (const float*)d_in[2];
    const float* b1 = (const float*)d_in[3];
    const float* W2 = (const float*)d_in[4];
    const float* b2 = (const float*)d_in[5];
    float* out = (float*)d_out;

    int n = in_sizes[0] / FDIM;   // 100000
    int e = in_sizes[1] / 2;      // 1600000

    const int ws_bytes = 64 * WP_STRIDE * sizeof(unsigned);  // 34816
    cudaFuncSetAttribute(gemm1_k, cudaFuncAttributeMaxDynamicSharedMemorySize, ws_bytes);

    int nblk = (n + SCAN_TPB - 1) / SCAN_TPB;

    zero_probe_k<<<(n + 255) / 256, 256>>>((const unsigned long long*)ei, n);  // 1
    hist_k<<<(e + 255) / 256, 256>>>(ei, e);                                   // 2
    scan_phase1_k<<<nblk, SCAN_TPB>>>(n);                                      // 3 (also dinv)
    gemm1_k<<<(n + 127) / 128, 256, ws_bytes>>>(x, W1, n);                     // 4 <- ncu capture
    scan_phase3_k<<<nblk, SCAN_TPB>>>(n);                                      // 5
    fill_k<<<(e + 255) / 256, 256>>>(ei, e);                                   // 6

    long long w1t = (long long)n * 32;   // one warp per node
    pull1_k<<<(unsigned)((w1t + 255) / 256), 256>>>(b1, n);                    // 7

    gemm2_k<<<(n + 7) / 8, 128>>>(W2, n);                                      // 8

    long long p2t = (long long)n * 4;    // 4 threads per node
    pull2_k<<<(unsigned)((p2t + 255) / 256), 256>>>(b2, out, n);               // 9
}